// round 6
// baseline (speedup 1.0000x reference)
#include <cuda_runtime.h>
#include <cuda_fp16.h>

#define NNODES 100000
#define NEDGES 1600000

// ---- scratch (device globals; no allocation allowed) ----
__device__ int   g_counts[NNODES];
__device__ int   g_fill[NNODES];
__device__ int   g_rowptr[NNODES + 1];
__device__ int2  g_edge[NEDGES];          // {src, __float_as_int(w)}
__device__ __half g_suph[(size_t)NNODES * 64];   // fp16 support (GEMM out, agg in)
__device__ float  g_h[(size_t)NNODES * 64];      // fp32 hidden state

// ---------------------------------------------------------------- CSR build
__global__ void hist_kernel(const int* __restrict__ tgt) {
    int e = blockIdx.x * blockDim.x + threadIdx.x;
    if (e < NEDGES) atomicAdd(&g_counts[tgt[e]], 1);
}

// single-block exclusive scan over 100k counts -> rowptr; also zeroes g_fill
__global__ void scan_kernel() {
    __shared__ int sums[1024];
    int t = threadIdx.x;
    const int C = (NNODES + 1023) >> 10;   // 98
    int lo = t * C;
    int hi = lo + C; if (hi > NNODES) hi = NNODES;
    int s = 0;
    for (int i = lo; i < hi; i++) s += g_counts[i];
    sums[t] = s;
    __syncthreads();
    for (int off = 1; off < 1024; off <<= 1) {
        int v = sums[t];
        int add = (t >= off) ? sums[t - off] : 0;
        __syncthreads();
        sums[t] = v + add;
        __syncthreads();
    }
    int run = (t == 0) ? 0 : sums[t - 1];
    for (int i = lo; i < hi; i++) {
        g_rowptr[i] = run;
        g_fill[i] = 0;
        run += g_counts[i];
    }
    if (hi == NNODES) g_rowptr[NNODES] = run;   // == NEDGES (idempotent writers)
}

__global__ void scatter_kernel(const int* __restrict__ src,
                               const int* __restrict__ tgt,
                               const float* __restrict__ w) {
    int e = blockIdx.x * blockDim.x + threadIdx.x;
    if (e >= NEDGES) return;
    int t = tgt[e];
    int pos = g_rowptr[t] + atomicAdd(&g_fill[t], 1);
    int2 pk; pk.x = src[e]; pk.y = __float_as_int(w[e]);
    g_edge[pos] = pk;                     // single 8B store
}

// ---------------------------------------------------------------- dense GEMM
// Yh[nrows,M] (fp16) = X[nrows,K] (fp32) @ W[K,M] (fp32); fp32 accumulate,
// one fp16 rounding at the store. 64-row tile, 4x4 register tile,
// W staged in K-chunks of 64 rows (smem <= ~50KB -> 4 blocks/SM).
template <int K, int M>
__global__ void gemm_kernel(const float* __restrict__ X,
                            const float* __restrict__ W,
                            __half* __restrict__ Yh, int nrows) {
    constexpr int KC = (K < 64) ? K : 64;          // W chunk rows
    extern __shared__ float sm[];
    float* Ws = sm;                // KC*M
    float* Xs = sm + KC * M;       // 64*(K+4), padded vs bank conflicts
    const int nthr = blockDim.x * blockDim.y;
    const int tid  = threadIdx.y * blockDim.x + threadIdx.x;

    const int rowBase = blockIdx.x * 64;
    int rlim = nrows - rowBase; if (rlim > 64) rlim = 64;
    const int KV = K / 4;
    for (int i = tid; i < rlim * KV; i += nthr) {
        int r = i / KV, c = i - r * KV;
        float4 v = ((const float4*)X)[(size_t)(rowBase + r) * KV + c];
        *(float4*)&Xs[r * (K + 4) + c * 4] = v;
    }

    const int j  = threadIdx.x * 4;   // blockDim.x = M/4
    const int r0 = threadIdx.y * 4;   // blockDim.y = 16 -> 64 rows
    float acc[4][4];
#pragma unroll
    for (int r = 0; r < 4; r++)
#pragma unroll
        for (int c = 0; c < 4; c++) acc[r][c] = 0.f;

#pragma unroll
    for (int kb = 0; kb < K; kb += KC) {
        if (kb) __syncthreads();                   // prior chunk's compute done
        for (int i = tid; i < KC * M / 4; i += nthr)
            ((float4*)Ws)[i] = ((const float4*)W)[kb * M / 4 + i];
        __syncthreads();                           // Ws (and Xs on first pass) ready

#pragma unroll 8
        for (int kk = 0; kk < KC; kk++) {
            int k = kb + kk;
            float4 wv = *(const float4*)&Ws[kk * M + j];
            float x0 = Xs[(r0 + 0) * (K + 4) + k];
            float x1 = Xs[(r0 + 1) * (K + 4) + k];
            float x2 = Xs[(r0 + 2) * (K + 4) + k];
            float x3 = Xs[(r0 + 3) * (K + 4) + k];
            acc[0][0] = fmaf(x0, wv.x, acc[0][0]); acc[0][1] = fmaf(x0, wv.y, acc[0][1]);
            acc[0][2] = fmaf(x0, wv.z, acc[0][2]); acc[0][3] = fmaf(x0, wv.w, acc[0][3]);
            acc[1][0] = fmaf(x1, wv.x, acc[1][0]); acc[1][1] = fmaf(x1, wv.y, acc[1][1]);
            acc[1][2] = fmaf(x1, wv.z, acc[1][2]); acc[1][3] = fmaf(x1, wv.w, acc[1][3]);
            acc[2][0] = fmaf(x2, wv.x, acc[2][0]); acc[2][1] = fmaf(x2, wv.y, acc[2][1]);
            acc[2][2] = fmaf(x2, wv.z, acc[2][2]); acc[2][3] = fmaf(x2, wv.w, acc[2][3]);
            acc[3][0] = fmaf(x3, wv.x, acc[3][0]); acc[3][1] = fmaf(x3, wv.y, acc[3][1]);
            acc[3][2] = fmaf(x3, wv.z, acc[3][2]); acc[3][3] = fmaf(x3, wv.w, acc[3][3]);
        }
    }

#pragma unroll
    for (int r = 0; r < 4; r++) {
        int row = rowBase + r0 + r;
        if (row < nrows) {
            union { __half2 h2[2]; uint2 u; } cv;
            cv.h2[0] = __floats2half2_rn(acc[r][0], acc[r][1]);
            cv.h2[1] = __floats2half2_rn(acc[r][2], acc[r][3]);
            *(uint2*)&Yh[(size_t)row * M + j] = cv.u;   // 8B aligned: j multiple of 4
        }
    }
}

// ----------------------------------------------------- sparse aggregation, M=64
// warp per node; lane owns features (2*lane, 2*lane+1) via one half2 gather.
// fp32 accumulate; fused bias+relu(+residual); float2 output.
__global__ void agg64_kernel(const __half2* __restrict__ sup2,   // rows of 32 half2
                             const float* __restrict__ bias,
                             float* hout, const float* resid, int has_resid) {
    int gw   = (blockIdx.x * blockDim.x + threadIdx.x) >> 5;
    int lane = threadIdx.x & 31;
    if (gw >= NNODES) return;
    int e   = g_rowptr[gw];
    int end = g_rowptr[gw + 1];
    float a0 = 0.f, a1 = 0.f;
    for (; e + 8 <= end; e += 8) {
        int2 ed[8];
#pragma unroll
        for (int q = 0; q < 8; q++) ed[q] = g_edge[e + q];
        __half2 hv[8];
#pragma unroll
        for (int q = 0; q < 8; q++) hv[q] = sup2[(size_t)ed[q].x * 32 + lane];
#pragma unroll
        for (int q = 0; q < 8; q++) {
            float w = __int_as_float(ed[q].y);
            float2 f = __half22float2(hv[q]);
            a0 = fmaf(f.x, w, a0);
            a1 = fmaf(f.y, w, a1);
        }
    }
    for (; e < end; e++) {
        int2 ed = g_edge[e];
        float w = __int_as_float(ed.y);
        float2 f = __half22float2(sup2[(size_t)ed.x * 32 + lane]);
        a0 = fmaf(f.x, w, a0);
        a1 = fmaf(f.y, w, a1);
    }
    float2 bv = ((const float2*)bias)[lane];
    a0 = fmaxf(a0 + bv.x, 0.f);
    a1 = fmaxf(a1 + bv.y, 0.f);
    if (has_resid) {               // resid may alias hout: same-element RMW only
        float2 rv = ((const float2*)(resid + (size_t)gw * 64))[lane];
        a0 += rv.x; a1 += rv.y;
    }
    float2 o; o.x = a0; o.y = a1;
    ((float2*)(hout + (size_t)gw * 64))[lane] = o;
}

// ------------------------------------------- sparse aggregation + log_softmax, M=40
// rows of 20 half2; lanes 0..19 own features (2*lane, 2*lane+1).
__global__ void agg40_kernel(const __half2* __restrict__ sup2,   // rows of 20 half2
                             const float* __restrict__ bias,
                             float* __restrict__ out) {
    int gw   = (blockIdx.x * blockDim.x + threadIdx.x) >> 5;
    int lane = threadIdx.x & 31;
    if (gw >= NNODES) return;
    const bool act = (lane < 20);
    int e   = g_rowptr[gw];
    int end = g_rowptr[gw + 1];
    float a0 = 0.f, a1 = 0.f;
    for (; e + 4 <= end; e += 4) {
        int2 ed[4];
#pragma unroll
        for (int q = 0; q < 4; q++) ed[q] = g_edge[e + q];
        __half2 hv[4];
#pragma unroll
        for (int q = 0; q < 4; q++)
            hv[q] = act ? sup2[(size_t)ed[q].x * 20 + lane] : __half2(__float2half2_rn(0.f));
#pragma unroll
        for (int q = 0; q < 4; q++) {
            float w = __int_as_float(ed[q].y);
            float2 f = __half22float2(hv[q]);
            a0 = fmaf(f.x, w, a0);
            a1 = fmaf(f.y, w, a1);
        }
    }
    for (; e < end; e++) {
        int2 ed = g_edge[e];
        float w = __int_as_float(ed.y);
        float2 f = act ? __half22float2(sup2[(size_t)ed.x * 20 + lane])
                       : make_float2(0.f, 0.f);
        a0 = fmaf(f.x, w, a0);
        a1 = fmaf(f.y, w, a1);
    }
    if (act) {
        a0 += bias[2 * lane];
        a1 += bias[2 * lane + 1];
    }

    // log_softmax over 40 features (lanes 0..19 hold 2 each)
    float m = act ? fmaxf(a0, a1) : -3.4e38f;
#pragma unroll
    for (int o = 16; o; o >>= 1) m = fmaxf(m, __shfl_xor_sync(0xffffffffu, m, o));
    float ssum = act ? (__expf(a0 - m) + __expf(a1 - m)) : 0.f;
#pragma unroll
    for (int o = 16; o; o >>= 1) ssum += __shfl_xor_sync(0xffffffffu, ssum, o);
    float L = m + __logf(ssum);

    if (act) {
        float2 o2; o2.x = a0 - L; o2.y = a1 - L;
        ((float2*)(out + (size_t)gw * 40))[lane] = o2;
    }
}

// ---------------------------------------------------------------- launch
extern "C" void kernel_launch(void* const* d_in, const int* in_sizes, int n_in,
                              void* d_out, int out_size) {
    const float* x   = (const float*)d_in[0];
    const int*   src = (const int*)d_in[1];
    const int*   tgt = (const int*)d_in[2];
    const float* mw  = (const float*)d_in[3];
    const float* W0  = (const float*)d_in[4];  const float* b0 = (const float*)d_in[5];
    const float* W1  = (const float*)d_in[6];  const float* b1 = (const float*)d_in[7];
    const float* W2  = (const float*)d_in[8];  const float* b2 = (const float*)d_in[9];
    const float* W3  = (const float*)d_in[10]; const float* b3 = (const float*)d_in[11];
    float* out = (float*)d_out;

    // smem: Ws chunk (KC*M) + Xs (64*(K+4))
    const int S0 = (64 * 64 + 64 * (128 + 4)) * 4;   // 50176 (needs opt-in)
    const int S1 = (64 * 64 + 64 * (64 + 4)) * 4;    // 33792
    const int S3 = (64 * 40 + 64 * (64 + 4)) * 4;    // 27648
    cudaFuncSetAttribute(gemm_kernel<128, 64>, cudaFuncAttributeMaxDynamicSharedMemorySize, S0);

    void* p;
    cudaGetSymbolAddress(&p, g_suph);   __half* sup = (__half*)p;
    cudaGetSymbolAddress(&p, g_h);      float*  h   = (float*)p;
    void* pcnt; cudaGetSymbolAddress(&pcnt, g_counts);
    __half2* sup2 = (__half2*)sup;

    // ---- CSR build (serial; side-stream fork measured -150us, keep serial) ----
    cudaMemsetAsync(pcnt, 0, NNODES * sizeof(int), 0);
    hist_kernel<<<(NEDGES + 255) / 256, 256>>>(tgt);
    scan_kernel<<<1, 1024>>>();
    scatter_kernel<<<(NEDGES + 255) / 256, 256>>>(src, tgt, mw);

    const int gblocks = (NNODES + 63) / 64;
    const int ablocks = ((NNODES * 32) + 255) / 256;

    // layer 0: h = relu(A @ (x W0) + b0)
    gemm_kernel<128, 64><<<gblocks, dim3(16, 16), S0>>>(x, W0, sup, NNODES);
    agg64_kernel<<<ablocks, 256>>>(sup2, b0, h, nullptr, 0);
    // layer 1: h = relu(A @ (h W1) + b1) + h
    gemm_kernel<64, 64><<<gblocks, dim3(16, 16), S1>>>(h, W1, sup, NNODES);
    agg64_kernel<<<ablocks, 256>>>(sup2, b1, h, h, 1);
    // layer 2
    gemm_kernel<64, 64><<<gblocks, dim3(16, 16), S1>>>(h, W2, sup, NNODES);
    agg64_kernel<<<ablocks, 256>>>(sup2, b2, h, h, 1);
    // layer 3: out = log_softmax(A @ (h W3) + b3)
    gemm_kernel<64, 40><<<gblocks, dim3(10, 16), S3>>>(h, W3, sup, NNODES);
    agg40_kernel<<<ablocks, 256>>>(sup2, b3, out);
}

// round 7
// speedup vs baseline: 1.6548x; 1.6548x over previous
#include <cuda_runtime.h>

#define NNODES 100000
#define NEDGES 1600000
#define SCANB  ((NNODES + 255) / 256)    // 391 scan blocks

// ---- scratch (device globals; no allocation allowed) ----
__device__ int   g_counts[NNODES];
__device__ int   g_fill[NNODES];
__device__ int   g_rowptr[NNODES + 1];
__device__ int   g_partial[SCANB];
__device__ int2  g_edge[NEDGES];          // {src, __float_as_int(w)}
__device__ float g_support[(size_t)NNODES * 64];
__device__ float g_h[(size_t)NNODES * 64];

// ---------------------------------------------------------------- CSR build
__global__ void hist_kernel(const int* __restrict__ tgt) {
    int e = blockIdx.x * blockDim.x + threadIdx.x;
    if (e < NEDGES) atomicAdd(&g_counts[tgt[e]], 1);
}

// per-block sum of 256 counts
__global__ void scanA_kernel() {
    __shared__ int s[256];
    int i = blockIdx.x * 256 + threadIdx.x;
    s[threadIdx.x] = (i < NNODES) ? g_counts[i] : 0;
    __syncthreads();
    for (int off = 128; off; off >>= 1) {
        if (threadIdx.x < off) s[threadIdx.x] += s[threadIdx.x + off];
        __syncthreads();
    }
    if (threadIdx.x == 0) g_partial[blockIdx.x] = s[0];
}

// single block: exclusive scan over SCANB partials
__global__ void scanB_kernel() {
    __shared__ int s[512];
    int t = threadIdx.x;
    s[t] = (t < SCANB) ? g_partial[t] : 0;
    __syncthreads();
    for (int off = 1; off < 512; off <<= 1) {
        int v = s[t];
        int add = (t >= off) ? s[t - off] : 0;
        __syncthreads();
        s[t] = v + add;
        __syncthreads();
    }
    if (t < SCANB) g_partial[t] = (t == 0) ? 0 : s[t - 1];   // exclusive
}

// per-block: exclusive scan of its 256 counts + base -> rowptr; zero fill
__global__ void scanC_kernel() {
    __shared__ int s[256];
    int t = threadIdx.x;
    int i = blockIdx.x * 256 + t;
    int c = (i < NNODES) ? g_counts[i] : 0;
    s[t] = c;
    __syncthreads();
    for (int off = 1; off < 256; off <<= 1) {
        int v = s[t];
        int add = (t >= off) ? s[t - off] : 0;
        __syncthreads();
        s[t] = v + add;
        __syncthreads();
    }
    if (i < NNODES) {
        g_rowptr[i] = g_partial[blockIdx.x] + s[t] - c;   // exclusive
        g_fill[i] = 0;
    }
    if (i == 0) g_rowptr[NNODES] = NEDGES;
}

__global__ void scatter_kernel(const int* __restrict__ src,
                               const int* __restrict__ tgt,
                               const float* __restrict__ w) {
    int e = blockIdx.x * blockDim.x + threadIdx.x;
    if (e >= NEDGES) return;
    int t = tgt[e];
    int pos = g_rowptr[t] + atomicAdd(&g_fill[t], 1);
    int2 pk; pk.x = src[e]; pk.y = __float_as_int(w[e]);
    g_edge[pos] = pk;                     // single 8B store
}

// ---------------------------------------------------------------- dense GEMM
// Y[nrows,M] = X[nrows,K] @ W[K,M].  64-row block tile, 4x4 register tile.
// W staged in K-chunks of 64 rows (smem <= ~50KB -> better occupancy).
template <int K, int M>
__global__ void gemm_kernel(const float* __restrict__ X,
                            const float* __restrict__ W,
                            float* __restrict__ Y, int nrows) {
    constexpr int KC = (K < 64) ? K : 64;          // W chunk rows
    extern __shared__ float sm[];
    float* Ws = sm;                // KC*M
    float* Xs = sm + KC * M;       // 64*(K+4), padded vs bank conflicts
    const int nthr = blockDim.x * blockDim.y;
    const int tid  = threadIdx.y * blockDim.x + threadIdx.x;

    const int rowBase = blockIdx.x * 64;
    int rlim = nrows - rowBase; if (rlim > 64) rlim = 64;
    const int KV = K / 4;
    for (int i = tid; i < rlim * KV; i += nthr) {
        int r = i / KV, c = i - r * KV;
        float4 v = ((const float4*)X)[(size_t)(rowBase + r) * KV + c];
        *(float4*)&Xs[r * (K + 4) + c * 4] = v;
    }

    const int j  = threadIdx.x * 4;   // blockDim.x = M/4
    const int r0 = threadIdx.y * 4;   // blockDim.y = 16 -> 64 rows
    float acc[4][4];
#pragma unroll
    for (int r = 0; r < 4; r++)
#pragma unroll
        for (int c = 0; c < 4; c++) acc[r][c] = 0.f;

#pragma unroll
    for (int kb = 0; kb < K; kb += KC) {
        if (kb) __syncthreads();                   // prior chunk's compute done
        for (int i = tid; i < KC * M / 4; i += nthr)
            ((float4*)Ws)[i] = ((const float4*)W)[kb * M / 4 + i];
        __syncthreads();                           // Ws (and Xs on first pass) ready

#pragma unroll 8
        for (int kk = 0; kk < KC; kk++) {
            int k = kb + kk;
            float4 wv = *(const float4*)&Ws[kk * M + j];
            float x0 = Xs[(r0 + 0) * (K + 4) + k];
            float x1 = Xs[(r0 + 1) * (K + 4) + k];
            float x2 = Xs[(r0 + 2) * (K + 4) + k];
            float x3 = Xs[(r0 + 3) * (K + 4) + k];
            acc[0][0] = fmaf(x0, wv.x, acc[0][0]); acc[0][1] = fmaf(x0, wv.y, acc[0][1]);
            acc[0][2] = fmaf(x0, wv.z, acc[0][2]); acc[0][3] = fmaf(x0, wv.w, acc[0][3]);
            acc[1][0] = fmaf(x1, wv.x, acc[1][0]); acc[1][1] = fmaf(x1, wv.y, acc[1][1]);
            acc[1][2] = fmaf(x1, wv.z, acc[1][2]); acc[1][3] = fmaf(x1, wv.w, acc[1][3]);
            acc[2][0] = fmaf(x2, wv.x, acc[2][0]); acc[2][1] = fmaf(x2, wv.y, acc[2][1]);
            acc[2][2] = fmaf(x2, wv.z, acc[2][2]); acc[2][3] = fmaf(x2, wv.w, acc[2][3]);
            acc[3][0] = fmaf(x3, wv.x, acc[3][0]); acc[3][1] = fmaf(x3, wv.y, acc[3][1]);
            acc[3][2] = fmaf(x3, wv.z, acc[3][2]); acc[3][3] = fmaf(x3, wv.w, acc[3][3]);
        }
    }

#pragma unroll
    for (int r = 0; r < 4; r++) {
        int row = rowBase + r0 + r;
        if (row < nrows) {
            float4 o; o.x = acc[r][0]; o.y = acc[r][1]; o.z = acc[r][2]; o.w = acc[r][3];
            *(float4*)&Y[(size_t)row * M + j] = o;
        }
    }
}

// ----------------------------------------------------- sparse aggregation, M=64
// TWO nodes per warp: lanes 0-15 -> node 2w, lanes 16-31 -> node 2w+1.
// Each lane owns 4 features (sub*4..sub*4+3) via one float4 gather per edge.
// ~3 warp-issues/edge vs 5 in the old layout. Fused bias+relu(+residual).
__global__ void agg64_kernel(const float4* __restrict__ sup4,  // rows of 16 float4
                             const float* __restrict__ bias,
                             float* hout, const float* resid, int has_resid) {
    int gw   = (blockIdx.x * blockDim.x + threadIdx.x) >> 5;
    int lane = threadIdx.x & 31;
    int half = lane >> 4, sub = lane & 15;
    int node = gw * 2 + half;
    if (node >= NNODES) return;
    int e   = g_rowptr[node];
    int end = g_rowptr[node + 1];
    float4 a = make_float4(0.f, 0.f, 0.f, 0.f);
    for (; e + 4 <= end; e += 4) {
        int2 e0 = g_edge[e], e1 = g_edge[e + 1], e2 = g_edge[e + 2], e3 = g_edge[e + 3];
        float4 v0 = sup4[(size_t)e0.x * 16 + sub];
        float4 v1 = sup4[(size_t)e1.x * 16 + sub];
        float4 v2 = sup4[(size_t)e2.x * 16 + sub];
        float4 v3 = sup4[(size_t)e3.x * 16 + sub];
        float w0 = __int_as_float(e0.y), w1 = __int_as_float(e1.y);
        float w2 = __int_as_float(e2.y), w3 = __int_as_float(e3.y);
        a.x = fmaf(v0.x, w0, a.x); a.y = fmaf(v0.y, w0, a.y);
        a.z = fmaf(v0.z, w0, a.z); a.w = fmaf(v0.w, w0, a.w);
        a.x = fmaf(v1.x, w1, a.x); a.y = fmaf(v1.y, w1, a.y);
        a.z = fmaf(v1.z, w1, a.z); a.w = fmaf(v1.w, w1, a.w);
        a.x = fmaf(v2.x, w2, a.x); a.y = fmaf(v2.y, w2, a.y);
        a.z = fmaf(v2.z, w2, a.z); a.w = fmaf(v2.w, w2, a.w);
        a.x = fmaf(v3.x, w3, a.x); a.y = fmaf(v3.y, w3, a.y);
        a.z = fmaf(v3.z, w3, a.z); a.w = fmaf(v3.w, w3, a.w);
    }
    for (; e < end; e++) {
        int2 ed = g_edge[e];
        float4 v = sup4[(size_t)ed.x * 16 + sub];
        float w = __int_as_float(ed.y);
        a.x = fmaf(v.x, w, a.x); a.y = fmaf(v.y, w, a.y);
        a.z = fmaf(v.z, w, a.z); a.w = fmaf(v.w, w, a.w);
    }
    float4 bv = ((const float4*)bias)[sub];
    a.x = fmaxf(a.x + bv.x, 0.f);
    a.y = fmaxf(a.y + bv.y, 0.f);
    a.z = fmaxf(a.z + bv.z, 0.f);
    a.w = fmaxf(a.w + bv.w, 0.f);
    if (has_resid) {               // resid may alias hout: same-element RMW only
        float4 rv = ((const float4*)(resid + (size_t)node * 64))[sub];
        a.x += rv.x; a.y += rv.y; a.z += rv.z; a.w += rv.w;
    }
    ((float4*)(hout + (size_t)node * 64))[sub] = a;
}

// ------------------------------------------- sparse aggregation + log_softmax, M=40
__global__ void agg40_kernel(const float* __restrict__ sup,
                             const float* __restrict__ bias,
                             float* __restrict__ out) {
    int gw   = (blockIdx.x * blockDim.x + threadIdx.x) >> 5;
    int lane = threadIdx.x & 31;
    if (gw >= NNODES) return;
    int e   = g_rowptr[gw];
    int end = g_rowptr[gw + 1];
    float a0 = 0.f, a1 = 0.f;
    for (; e + 4 <= end; e += 4) {
        int2 e0 = g_edge[e], e1 = g_edge[e + 1], e2 = g_edge[e + 2], e3 = g_edge[e + 3];
        const float* p0 = sup + (size_t)e0.x * 40;
        const float* p1 = sup + (size_t)e1.x * 40;
        const float* p2 = sup + (size_t)e2.x * 40;
        const float* p3 = sup + (size_t)e3.x * 40;
        float w0 = __int_as_float(e0.y), w1 = __int_as_float(e1.y);
        float w2 = __int_as_float(e2.y), w3 = __int_as_float(e3.y);
        a0 = fmaf(p0[lane], w0, a0);
        a0 = fmaf(p1[lane], w1, a0);
        a0 = fmaf(p2[lane], w2, a0);
        a0 = fmaf(p3[lane], w3, a0);
        if (lane < 8) {
            a1 = fmaf(p0[32 + lane], w0, a1);
            a1 = fmaf(p1[32 + lane], w1, a1);
            a1 = fmaf(p2[32 + lane], w2, a1);
            a1 = fmaf(p3[32 + lane], w3, a1);
        }
    }
    for (; e < end; e++) {
        int2 ed = g_edge[e];
        const float* p = sup + (size_t)ed.x * 40;
        float w = __int_as_float(ed.y);
        a0 = fmaf(p[lane], w, a0);
        if (lane < 8) a1 = fmaf(p[32 + lane], w, a1);
    }
    a0 += bias[lane];
    if (lane < 8) a1 += bias[32 + lane];

    // log_softmax over 40 features distributed over the warp
    float m = a0;
    if (lane < 8) m = fmaxf(m, a1);
#pragma unroll
    for (int o = 16; o; o >>= 1) m = fmaxf(m, __shfl_xor_sync(0xffffffffu, m, o));
    float ssum = __expf(a0 - m) + ((lane < 8) ? __expf(a1 - m) : 0.f);
#pragma unroll
    for (int o = 16; o; o >>= 1) ssum += __shfl_xor_sync(0xffffffffu, ssum, o);
    float L = m + __logf(ssum);

    out[(size_t)gw * 40 + lane] = a0 - L;
    if (lane < 8) out[(size_t)gw * 40 + 32 + lane] = a1 - L;
}

// ---------------------------------------------------------------- launch
extern "C" void kernel_launch(void* const* d_in, const int* in_sizes, int n_in,
                              void* d_out, int out_size) {
    const float* x   = (const float*)d_in[0];
    const int*   src = (const int*)d_in[1];
    const int*   tgt = (const int*)d_in[2];
    const float* mw  = (const float*)d_in[3];
    const float* W0  = (const float*)d_in[4];  const float* b0 = (const float*)d_in[5];
    const float* W1  = (const float*)d_in[6];  const float* b1 = (const float*)d_in[7];
    const float* W2  = (const float*)d_in[8];  const float* b2 = (const float*)d_in[9];
    const float* W3  = (const float*)d_in[10]; const float* b3 = (const float*)d_in[11];
    float* out = (float*)d_out;

    // smem: Ws chunk (KC*M) + Xs (64*(K+4))
    const int S0 = (64 * 64 + 64 * (128 + 4)) * 4;   // 50176 (needs opt-in)
    const int S1 = (64 * 64 + 64 * (64 + 4)) * 4;    // 33792
    const int S3 = (64 * 40 + 64 * (64 + 4)) * 4;    // 27648
    cudaFuncSetAttribute(gemm_kernel<128, 64>, cudaFuncAttributeMaxDynamicSharedMemorySize, S0);

    void* p;
    cudaGetSymbolAddress(&p, g_support); float* sup = (float*)p;
    cudaGetSymbolAddress(&p, g_h);       float* h   = (float*)p;
    void* pcnt; cudaGetSymbolAddress(&pcnt, g_counts);

    // ---- CSR build (serial; parallel 3-phase scan) ----
    cudaMemsetAsync(pcnt, 0, NNODES * sizeof(int), 0);
    hist_kernel<<<(NEDGES + 255) / 256, 256>>>(tgt);
    scanA_kernel<<<SCANB, 256>>>();
    scanB_kernel<<<1, 512>>>();
    scanC_kernel<<<SCANB, 256>>>();
    scatter_kernel<<<(NEDGES + 255) / 256, 256>>>(src, tgt, mw);

    const int gblocks = (NNODES + 63) / 64;
    const int a64blocks = (((NNODES + 1) / 2) * 32 + 255) / 256;   // 2 nodes/warp
    const int a40blocks = ((NNODES * 32) + 255) / 256;

    // layer 0: h = relu(A @ (x W0) + b0)
    gemm_kernel<128, 64><<<gblocks, dim3(16, 16), S0>>>(x, W0, sup, NNODES);
    agg64_kernel<<<a64blocks, 256>>>((const float4*)sup, b0, h, nullptr, 0);
    // layer 1: h = relu(A @ (h W1) + b1) + h
    gemm_kernel<64, 64><<<gblocks, dim3(16, 16), S1>>>(h, W1, sup, NNODES);
    agg64_kernel<<<a64blocks, 256>>>((const float4*)sup, b1, h, h, 1);
    // layer 2
    gemm_kernel<64, 64><<<gblocks, dim3(16, 16), S1>>>(h, W2, sup, NNODES);
    agg64_kernel<<<a64blocks, 256>>>((const float4*)sup, b2, h, h, 1);
    // layer 3: out = log_softmax(A @ (h W3) + b3)
    gemm_kernel<64, 40><<<gblocks, dim3(10, 16), S3>>>(h, W3, sup, NNODES);
    agg40_kernel<<<a40blocks, 256>>>(sup, b3, out);
}

// round 9
// speedup vs baseline: 1.8430x; 1.1137x over previous
#include <cuda_runtime.h>
#include <cuda_fp16.h>

#define NNODES 100000
#define NEDGES 1600000
#define SCANB  ((NNODES + 255) / 256)    // 391 scan blocks

// ---- scratch (device globals; no allocation allowed) ----
__device__ int    g_counts[NNODES];
__device__ int    g_fill[NNODES];
__device__ int    g_rowptr[NNODES + 1];
__device__ int    g_partial[SCANB];
__device__ int2   g_edge[NEDGES];         // {src, __float_as_int(w)}
__device__ __half g_suph[(size_t)NNODES * 64];   // fp16 support (GEMM out, agg in)
__device__ float  g_h[(size_t)NNODES * 64];      // fp32 hidden state

// ---------------------------------------------------------------- CSR build
__global__ void hist_kernel(const int* __restrict__ tgt) {
    int e = blockIdx.x * blockDim.x + threadIdx.x;
    if (e < NEDGES) atomicAdd(&g_counts[tgt[e]], 1);
}

// per-block sum of 256 counts
__global__ void scanA_kernel() {
    __shared__ int s[256];
    int i = blockIdx.x * 256 + threadIdx.x;
    s[threadIdx.x] = (i < NNODES) ? g_counts[i] : 0;
    __syncthreads();
    for (int off = 128; off; off >>= 1) {
        if (threadIdx.x < off) s[threadIdx.x] += s[threadIdx.x + off];
        __syncthreads();
    }
    if (threadIdx.x == 0) g_partial[blockIdx.x] = s[0];
}

// single block: exclusive scan over SCANB partials
__global__ void scanB_kernel() {
    __shared__ int s[512];
    int t = threadIdx.x;
    s[t] = (t < SCANB) ? g_partial[t] : 0;
    __syncthreads();
    for (int off = 1; off < 512; off <<= 1) {
        int v = s[t];
        int add = (t >= off) ? s[t - off] : 0;
        __syncthreads();
        s[t] = v + add;
        __syncthreads();
    }
    if (t < SCANB) g_partial[t] = (t == 0) ? 0 : s[t - 1];   // exclusive
}

// per-block: exclusive scan of its 256 counts + base -> rowptr; zero fill
__global__ void scanC_kernel() {
    __shared__ int s[256];
    int t = threadIdx.x;
    int i = blockIdx.x * 256 + t;
    int c = (i < NNODES) ? g_counts[i] : 0;
    s[t] = c;
    __syncthreads();
    for (int off = 1; off < 256; off <<= 1) {
        int v = s[t];
        int add = (t >= off) ? s[t - off] : 0;
        __syncthreads();
        s[t] = v + add;
        __syncthreads();
    }
    if (i < NNODES) {
        g_rowptr[i] = g_partial[blockIdx.x] + s[t] - c;   // exclusive
        g_fill[i] = 0;
    }
    if (i == 0) g_rowptr[NNODES] = NEDGES;
}

__global__ void scatter_kernel(const int* __restrict__ src,
                               const int* __restrict__ tgt,
                               const float* __restrict__ w) {
    int e = blockIdx.x * blockDim.x + threadIdx.x;
    if (e >= NEDGES) return;
    int t = tgt[e];
    int pos = g_rowptr[t] + atomicAdd(&g_fill[t], 1);
    int2 pk; pk.x = src[e]; pk.y = __float_as_int(w[e]);
    g_edge[pos] = pk;                     // single 8B store
}

// ---------------------------------------------------------------- dense GEMM
// Yh[nrows,M] (fp16) = X[nrows,K] (fp32) @ W[K,M] (fp32); fp32 accumulate,
// single fp16 rounding at the store. 64-row tile, 4x4 register tile,
// W staged in K-chunks of 64 rows.
template <int K, int M>
__global__ void gemm_kernel(const float* __restrict__ X,
                            const float* __restrict__ W,
                            __half* __restrict__ Yh, int nrows) {
    constexpr int KC = (K < 64) ? K : 64;          // W chunk rows
    extern __shared__ float sm[];
    float* Ws = sm;                // KC*M
    float* Xs = sm + KC * M;       // 64*(K+4), padded vs bank conflicts
    const int nthr = blockDim.x * blockDim.y;
    const int tid  = threadIdx.y * blockDim.x + threadIdx.x;

    const int rowBase = blockIdx.x * 64;
    int rlim = nrows - rowBase; if (rlim > 64) rlim = 64;
    const int KV = K / 4;
    for (int i = tid; i < rlim * KV; i += nthr) {
        int r = i / KV, c = i - r * KV;
        float4 v = ((const float4*)X)[(size_t)(rowBase + r) * KV + c];
        *(float4*)&Xs[r * (K + 4) + c * 4] = v;
    }

    const int j  = threadIdx.x * 4;   // blockDim.x = M/4
    const int r0 = threadIdx.y * 4;   // blockDim.y = 16 -> 64 rows
    float acc[4][4];
#pragma unroll
    for (int r = 0; r < 4; r++)
#pragma unroll
        for (int c = 0; c < 4; c++) acc[r][c] = 0.f;

#pragma unroll
    for (int kb = 0; kb < K; kb += KC) {
        if (kb) __syncthreads();                   // prior chunk's compute done
        for (int i = tid; i < KC * M / 4; i += nthr)
            ((float4*)Ws)[i] = ((const float4*)W)[kb * M / 4 + i];
        __syncthreads();                           // Ws (and Xs on first pass) ready

#pragma unroll 8
        for (int kk = 0; kk < KC; kk++) {
            int k = kb + kk;
            float4 wv = *(const float4*)&Ws[kk * M + j];
            float x0 = Xs[(r0 + 0) * (K + 4) + k];
            float x1 = Xs[(r0 + 1) * (K + 4) + k];
            float x2 = Xs[(r0 + 2) * (K + 4) + k];
            float x3 = Xs[(r0 + 3) * (K + 4) + k];
            acc[0][0] = fmaf(x0, wv.x, acc[0][0]); acc[0][1] = fmaf(x0, wv.y, acc[0][1]);
            acc[0][2] = fmaf(x0, wv.z, acc[0][2]); acc[0][3] = fmaf(x0, wv.w, acc[0][3]);
            acc[1][0] = fmaf(x1, wv.x, acc[1][0]); acc[1][1] = fmaf(x1, wv.y, acc[1][1]);
            acc[1][2] = fmaf(x1, wv.z, acc[1][2]); acc[1][3] = fmaf(x1, wv.w, acc[1][3]);
            acc[2][0] = fmaf(x2, wv.x, acc[2][0]); acc[2][1] = fmaf(x2, wv.y, acc[2][1]);
            acc[2][2] = fmaf(x2, wv.z, acc[2][2]); acc[2][3] = fmaf(x2, wv.w, acc[2][3]);
            acc[3][0] = fmaf(x3, wv.x, acc[3][0]); acc[3][1] = fmaf(x3, wv.y, acc[3][1]);
            acc[3][2] = fmaf(x3, wv.z, acc[3][2]); acc[3][3] = fmaf(x3, wv.w, acc[3][3]);
        }
    }

#pragma unroll
    for (int r = 0; r < 4; r++) {
        int row = rowBase + r0 + r;
        if (row < nrows) {
            union { __half2 h2[2]; uint2 u; } cv;
            cv.h2[0] = __floats2half2_rn(acc[r][0], acc[r][1]);
            cv.h2[1] = __floats2half2_rn(acc[r][2], acc[r][3]);
            *(uint2*)&Yh[(size_t)row * M + j] = cv.u;   // 8B aligned (j mult of 4)
        }
    }
}

// ----------------------------------------------------- sparse aggregation, M=64
// TWO nodes per warp: lanes 0-15 -> node 2w, 16-31 -> node 2w+1.
// Lane owns 4 features (sub*4..+3) via one 8B fp16 gather per edge
// (full row = ONE 128B line). fp32 accumulate; fused bias+relu(+residual).
__global__ void agg64_kernel(const __half* __restrict__ suph,
                             const float* __restrict__ bias,
                             float* hout, const float* resid, int has_resid) {
    int gw   = (blockIdx.x * blockDim.x + threadIdx.x) >> 5;
    int lane = threadIdx.x & 31;
    int half = lane >> 4, sub = lane & 15;
    int node = gw * 2 + half;
    if (node >= NNODES) return;
    int e   = g_rowptr[node];
    int end = g_rowptr[node + 1];
    float4 a = make_float4(0.f, 0.f, 0.f, 0.f);
    for (; e + 4 <= end; e += 4) {
        int2 e0 = g_edge[e], e1 = g_edge[e + 1], e2 = g_edge[e + 2], e3 = g_edge[e + 3];
        uint2 r0 = *(const uint2*)&suph[(size_t)e0.x * 64 + sub * 4];
        uint2 r1 = *(const uint2*)&suph[(size_t)e1.x * 64 + sub * 4];
        uint2 r2 = *(const uint2*)&suph[(size_t)e2.x * 64 + sub * 4];
        uint2 r3 = *(const uint2*)&suph[(size_t)e3.x * 64 + sub * 4];
        float w0 = __int_as_float(e0.y), w1 = __int_as_float(e1.y);
        float w2 = __int_as_float(e2.y), w3 = __int_as_float(e3.y);
        float2 fa, fb;
        fa = __half22float2(*(__half2*)&r0.x); fb = __half22float2(*(__half2*)&r0.y);
        a.x = fmaf(fa.x, w0, a.x); a.y = fmaf(fa.y, w0, a.y);
        a.z = fmaf(fb.x, w0, a.z); a.w = fmaf(fb.y, w0, a.w);
        fa = __half22float2(*(__half2*)&r1.x); fb = __half22float2(*(__half2*)&r1.y);
        a.x = fmaf(fa.x, w1, a.x); a.y = fmaf(fa.y, w1, a.y);
        a.z = fmaf(fb.x, w1, a.z); a.w = fmaf(fb.y, w1, a.w);
        fa = __half22float2(*(__half2*)&r2.x); fb = __half22float2(*(__half2*)&r2.y);
        a.x = fmaf(fa.x, w2, a.x); a.y = fmaf(fa.y, w2, a.y);
        a.z = fmaf(fb.x, w2, a.z); a.w = fmaf(fb.y, w2, a.w);
        fa = __half22float2(*(__half2*)&r3.x); fb = __half22float2(*(__half2*)&r3.y);
        a.x = fmaf(fa.x, w3, a.x); a.y = fmaf(fa.y, w3, a.y);
        a.z = fmaf(fb.x, w3, a.z); a.w = fmaf(fb.y, w3, a.w);
    }
    for (; e < end; e++) {
        int2 ed = g_edge[e];
        uint2 rv = *(const uint2*)&suph[(size_t)ed.x * 64 + sub * 4];
        float w = __int_as_float(ed.y);
        float2 fa = __half22float2(*(__half2*)&rv.x);
        float2 fb = __half22float2(*(__half2*)&rv.y);
        a.x = fmaf(fa.x, w, a.x); a.y = fmaf(fa.y, w, a.y);
        a.z = fmaf(fb.x, w, a.z); a.w = fmaf(fb.y, w, a.w);
    }
    float4 bv = ((const float4*)bias)[sub];
    a.x = fmaxf(a.x + bv.x, 0.f);
    a.y = fmaxf(a.y + bv.y, 0.f);
    a.z = fmaxf(a.z + bv.z, 0.f);
    a.w = fmaxf(a.w + bv.w, 0.f);
    if (has_resid) {               // resid may alias hout: same-element RMW only
        float4 rv = ((const float4*)(resid + (size_t)node * 64))[sub];
        a.x += rv.x; a.y += rv.y; a.z += rv.z; a.w += rv.w;
    }
    ((float4*)(hout + (size_t)node * 64))[sub] = a;
}

// ------------------------------------------- sparse aggregation + log_softmax, M=40
// TWO nodes per warp; lanes sub<10 own 4 features via one 8B fp16 gather
// (row = 80B). Warp-half (width 16) reductions for log_softmax.
__global__ void agg40_kernel(const __half* __restrict__ suph,
                             const float* __restrict__ bias,
                             float* __restrict__ out) {
    int gw   = (blockIdx.x * blockDim.x + threadIdx.x) >> 5;
    int lane = threadIdx.x & 31;
    int half = lane >> 4, sub = lane & 15;
    int node = gw * 2 + half;
    if (node >= NNODES) return;
    const bool act = (sub < 10);
    int e   = g_rowptr[node];
    int end = g_rowptr[node + 1];
    float4 a = make_float4(0.f, 0.f, 0.f, 0.f);
    for (; e + 4 <= end; e += 4) {
        int2 e0 = g_edge[e], e1 = g_edge[e + 1], e2 = g_edge[e + 2], e3 = g_edge[e + 3];
        uint2 r0 = make_uint2(0, 0), r1 = r0, r2 = r0, r3 = r0;
        if (act) {
            r0 = *(const uint2*)&suph[(size_t)e0.x * 40 + sub * 4];
            r1 = *(const uint2*)&suph[(size_t)e1.x * 40 + sub * 4];
            r2 = *(const uint2*)&suph[(size_t)e2.x * 40 + sub * 4];
            r3 = *(const uint2*)&suph[(size_t)e3.x * 40 + sub * 4];
        }
        float w0 = __int_as_float(e0.y), w1 = __int_as_float(e1.y);
        float w2 = __int_as_float(e2.y), w3 = __int_as_float(e3.y);
        float2 fa, fb;
        fa = __half22float2(*(__half2*)&r0.x); fb = __half22float2(*(__half2*)&r0.y);
        a.x = fmaf(fa.x, w0, a.x); a.y = fmaf(fa.y, w0, a.y);
        a.z = fmaf(fb.x, w0, a.z); a.w = fmaf(fb.y, w0, a.w);
        fa = __half22float2(*(__half2*)&r1.x); fb = __half22float2(*(__half2*)&r1.y);
        a.x = fmaf(fa.x, w1, a.x); a.y = fmaf(fa.y, w1, a.y);
        a.z = fmaf(fb.x, w1, a.z); a.w = fmaf(fb.y, w1, a.w);
        fa = __half22float2(*(__half2*)&r2.x); fb = __half22float2(*(__half2*)&r2.y);
        a.x = fmaf(fa.x, w2, a.x); a.y = fmaf(fa.y, w2, a.y);
        a.z = fmaf(fb.x, w2, a.z); a.w = fmaf(fb.y, w2, a.w);
        fa = __half22float2(*(__half2*)&r3.x); fb = __half22float2(*(__half2*)&r3.y);
        a.x = fmaf(fa.x, w3, a.x); a.y = fmaf(fa.y, w3, a.y);
        a.z = fmaf(fb.x, w3, a.z); a.w = fmaf(fb.y, w3, a.w);
    }
    for (; e < end; e++) {
        int2 ed = g_edge[e];
        uint2 rv = make_uint2(0, 0);
        if (act) rv = *(const uint2*)&suph[(size_t)ed.x * 40 + sub * 4];
        float w = __int_as_float(ed.y);
        float2 fa = __half22float2(*(__half2*)&rv.x);
        float2 fb = __half22float2(*(__half2*)&rv.y);
        a.x = fmaf(fa.x, w, a.x); a.y = fmaf(fa.y, w, a.y);
        a.z = fmaf(fb.x, w, a.z); a.w = fmaf(fb.y, w, a.w);
    }
    if (act) {
        float4 bv = ((const float4*)bias)[sub];
        a.x += bv.x; a.y += bv.y; a.z += bv.z; a.w += bv.w;
    }

    // log_softmax over 40 features held by lanes sub<10 (4 each); width-16 reduce
    float m = act ? fmaxf(fmaxf(a.x, a.y), fmaxf(a.z, a.w)) : -3.4e38f;
#pragma unroll
    for (int o = 8; o; o >>= 1) m = fmaxf(m, __shfl_xor_sync(0xffffffffu, m, o, 16));
    float ssum = act ? (__expf(a.x - m) + __expf(a.y - m) +
                        __expf(a.z - m) + __expf(a.w - m)) : 0.f;
#pragma unroll
    for (int o = 8; o; o >>= 1) ssum += __shfl_xor_sync(0xffffffffu, ssum, o, 16);
    float L = m + __logf(ssum);

    if (act) {
        float4 o4; o4.x = a.x - L; o4.y = a.y - L; o4.z = a.z - L; o4.w = a.w - L;
        ((float4*)(out + (size_t)node * 40))[sub] = o4;
    }
}

// ---------------------------------------------------------------- launch
extern "C" void kernel_launch(void* const* d_in, const int* in_sizes, int n_in,
                              void* d_out, int out_size) {
    const float* x   = (const float*)d_in[0];
    const int*   src = (const int*)d_in[1];
    const int*   tgt = (const int*)d_in[2];
    const float* mw  = (const float*)d_in[3];
    const float* W0  = (const float*)d_in[4];  const float* b0 = (const float*)d_in[5];
    const float* W1  = (const float*)d_in[6];  const float* b1 = (const float*)d_in[7];
    const float* W2  = (const float*)d_in[8];  const float* b2 = (const float*)d_in[9];
    const float* W3  = (const float*)d_in[10]; const float* b3 = (const float*)d_in[11];
    float* out = (float*)d_out;

    // smem: Ws chunk (KC*M) + Xs (64*(K+4))
    const int S0 = (64 * 64 + 64 * (128 + 4)) * 4;   // 50176 (needs opt-in)
    const int S1 = (64 * 64 + 64 * (64 + 4)) * 4;    // 33792
    const int S3 = (64 * 40 + 64 * (64 + 4)) * 4;    // 27648
    cudaFuncSetAttribute(gemm_kernel<128, 64>, cudaFuncAttributeMaxDynamicSharedMemorySize, S0);

    void* p;
    cudaGetSymbolAddress(&p, g_suph);  __half* sup = (__half*)p;
    cudaGetSymbolAddress(&p, g_h);     float*  h   = (float*)p;
    void* pcnt; cudaGetSymbolAddress(&pcnt, g_counts);

    // ---- CSR build (serial; parallel 3-phase scan) ----
    cudaMemsetAsync(pcnt, 0, NNODES * sizeof(int), 0);
    hist_kernel<<<(NEDGES + 255) / 256, 256>>>(tgt);
    scanA_kernel<<<SCANB, 256>>>();
    scanB_kernel<<<1, 512>>>();
    scanC_kernel<<<SCANB, 256>>>();
    scatter_kernel<<<(NEDGES + 255) / 256, 256>>>(src, tgt, mw);

    const int gblocks = (NNODES + 63) / 64;
    const int a2blocks = (((NNODES + 1) / 2) * 32 + 255) / 256;   // 2 nodes/warp

    // layer 0: h = relu(A @ (x W0) + b0)
    gemm_kernel<128, 64><<<gblocks, dim3(16, 16), S0>>>(x, W0, sup, NNODES);
    agg64_kernel<<<a2blocks, 256>>>(sup, b0, h, nullptr, 0);
    // layer 1: h = relu(A @ (h W1) + b1) + h
    gemm_kernel<64, 64><<<gblocks, dim3(16, 16), S1>>>(h, W1, sup, NNODES);
    agg64_kernel<<<a2blocks, 256>>>(sup, b1, h, h, 1);
    // layer 2
    gemm_kernel<64, 64><<<gblocks, dim3(16, 16), S1>>>(h, W2, sup, NNODES);
    agg64_kernel<<<a2blocks, 256>>>(sup, b2, h, h, 1);
    // layer 3: out = log_softmax(A @ (h W3) + b3)
    gemm_kernel<64, 40><<<gblocks, dim3(10, 16), S3>>>(h, W3, sup, NNODES);
    agg40_kernel<<<a2blocks, 256>>>(sup, b3, out);
}

// round 12
// speedup vs baseline: 2.1048x; 1.1421x over previous
#include <cuda_runtime.h>
#include <cuda_fp16.h>
#include <cstdint>

#define NNODES 100000
#define NEDGES 1600000
#define SCANB  ((NNODES + 255) / 256)    // 391 scan blocks

// ---- scratch (device globals; no allocation allowed) ----
__device__ int    g_counts[NNODES];
__device__ int    g_fill[NNODES];
__device__ int    g_rowptr[NNODES + 1];
__device__ int    g_partial[SCANB];
__device__ int2   g_edge[NEDGES];         // {src, __float_as_int(w)}
__device__ __half g_suph[(size_t)NNODES * 64];   // fp16 support (GEMM out, agg in)
__device__ float  g_h[(size_t)NNODES * 64];      // fp32 hidden state

// ---------------------------------------------------------------- CSR build
__global__ void hist_kernel(const int* __restrict__ tgt) {
    int e = blockIdx.x * blockDim.x + threadIdx.x;
    if (e < NEDGES) atomicAdd(&g_counts[tgt[e]], 1);
}

__global__ void scanA_kernel() {
    __shared__ int s[256];
    int i = blockIdx.x * 256 + threadIdx.x;
    s[threadIdx.x] = (i < NNODES) ? g_counts[i] : 0;
    __syncthreads();
    for (int off = 128; off; off >>= 1) {
        if (threadIdx.x < off) s[threadIdx.x] += s[threadIdx.x + off];
        __syncthreads();
    }
    if (threadIdx.x == 0) g_partial[blockIdx.x] = s[0];
}

__global__ void scanB_kernel() {
    __shared__ int s[512];
    int t = threadIdx.x;
    s[t] = (t < SCANB) ? g_partial[t] : 0;
    __syncthreads();
    for (int off = 1; off < 512; off <<= 1) {
        int v = s[t];
        int add = (t >= off) ? s[t - off] : 0;
        __syncthreads();
        s[t] = v + add;
        __syncthreads();
    }
    if (t < SCANB) g_partial[t] = (t == 0) ? 0 : s[t - 1];   // exclusive
}

__global__ void scanC_kernel() {
    __shared__ int s[256];
    int t = threadIdx.x;
    int i = blockIdx.x * 256 + t;
    int c = (i < NNODES) ? g_counts[i] : 0;
    s[t] = c;
    __syncthreads();
    for (int off = 1; off < 256; off <<= 1) {
        int v = s[t];
        int add = (t >= off) ? s[t - off] : 0;
        __syncthreads();
        s[t] = v + add;
        __syncthreads();
    }
    if (i < NNODES) {
        g_rowptr[i] = g_partial[blockIdx.x] + s[t] - c;   // exclusive
        g_fill[i] = 0;
    }
    if (i == 0) g_rowptr[NNODES] = NEDGES;
}

__global__ void scatter_kernel(const int* __restrict__ src,
                               const int* __restrict__ tgt,
                               const float* __restrict__ w) {
    int e = blockIdx.x * blockDim.x + threadIdx.x;
    if (e >= NEDGES) return;
    int t = tgt[e];
    int pos = g_rowptr[t] + atomicAdd(&g_fill[t], 1);
    int2 pk; pk.x = src[e]; pk.y = __float_as_int(w[e]);
    g_edge[pos] = pk;                     // single 8B store
}

// ---------------------------------------------------------------- helpers
__device__ __forceinline__ unsigned smem_u32(const void* p) {
    return (unsigned)__cvta_generic_to_shared(p);
}
__device__ __forceinline__ void ldsm_x4(unsigned& a0, unsigned& a1,
                                        unsigned& a2, unsigned& a3, unsigned addr) {
    asm volatile("ldmatrix.sync.aligned.m8n8.x4.shared.b16 {%0,%1,%2,%3}, [%4];"
                 : "=r"(a0), "=r"(a1), "=r"(a2), "=r"(a3) : "r"(addr));
}
__device__ __forceinline__ void ldsm_x2t(unsigned& b0, unsigned& b1, unsigned addr) {
    asm volatile("ldmatrix.sync.aligned.m8n8.x2.trans.shared.b16 {%0,%1}, [%2];"
                 : "=r"(b0), "=r"(b1) : "r"(addr));
}
__device__ __forceinline__ void mma16816(float* c, unsigned a0, unsigned a1,
                                         unsigned a2, unsigned a3,
                                         unsigned b0, unsigned b1) {
    asm volatile(
        "mma.sync.aligned.m16n8k16.row.col.f32.f16.f16.f32 "
        "{%0,%1,%2,%3},{%4,%5,%6,%7},{%8,%9},{%0,%1,%2,%3};"
        : "+f"(c[0]), "+f"(c[1]), "+f"(c[2]), "+f"(c[3])
        : "r"(a0), "r"(a1), "r"(a2), "r"(a3), "r"(b0), "r"(b1));
}
// unpack 4 halfs (as uint2 from an 8B load) into 2 float2
__device__ __forceinline__ void h4_to_f4(uint2 u, float2& lo, float2& hi) {
    __half2 ha = *reinterpret_cast<__half2*>(&u.x);
    __half2 hb = *reinterpret_cast<__half2*>(&u.y);
    lo = __half22float2(ha);
    hi = __half22float2(hb);
}

// ---------------------------------------------------------------- HMMA GEMM
// Yh[nrows,M] (fp16) = X[nrows,K] (fp32) @ W[K,M] (fp32) via fp16 HMMA,
// fp32 accumulate. 128-row block tile, 8 warps; warp = 16 rows x M cols.
template <int K, int M>
__global__ void gemm_kernel(const float* __restrict__ X,
                            const float* __restrict__ W,
                            __half* __restrict__ Yh, int nrows) {
    constexpr int KP = K + 8;           // padded X row (halfs)
    constexpr int MP = M + 8;           // padded W row (halfs)
    constexpr int NC = M / 8;           // n-chunks per warp
    extern __shared__ __half smh[];
    __half* Xs = smh;                   // [128][KP]
    __half* Ws = smh + 128 * KP;        // [K][MP]
    const int tid  = threadIdx.x;       // 256 threads
    const int wid  = tid >> 5;
    const int lane = tid & 31;
    const int rowBase = blockIdx.x * 128;

    // stage X (fp32 -> fp16), zero-fill rows past nrows
    for (int i = tid; i < 128 * (K / 2); i += 256) {
        int r = i / (K / 2), c2 = i % (K / 2);
        int grow = rowBase + r;
        float2 v = (grow < nrows) ? ((const float2*)X)[(size_t)grow * (K / 2) + c2]
                                  : make_float2(0.f, 0.f);
        *(__half2*)&Xs[r * KP + c2 * 2] = __floats2half2_rn(v.x, v.y);
    }
    // stage W (fp32 -> fp16)
    for (int i = tid; i < K * (M / 2); i += 256) {
        int k = i / (M / 2), c2 = i % (M / 2);
        float2 v = ((const float2*)W)[i];
        *(__half2*)&Ws[k * MP + c2 * 2] = __floats2half2_rn(v.x, v.y);
    }
    __syncthreads();

    const int rw = wid * 16;
    float acc[NC][4];
#pragma unroll
    for (int nc = 0; nc < NC; nc++) {
#pragma unroll
        for (int q = 0; q < 4; q++) acc[nc][q] = 0.f;
    }

#pragma unroll
    for (int kc = 0; kc < K / 16; kc++) {
        unsigned a0, a1, a2, a3;
        unsigned aaddr = smem_u32(&Xs[(rw + (lane & 15)) * KP + kc * 16 + (lane >> 4) * 8]);
        ldsm_x4(a0, a1, a2, a3, aaddr);
#pragma unroll
        for (int nc = 0; nc < NC; nc++) {
            unsigned b0, b1;
            unsigned baddr = smem_u32(&Ws[(kc * 16 + (lane & 15)) * MP + nc * 8]);
            ldsm_x2t(b0, b1, baddr);
            mma16816(acc[nc], a0, a1, a2, a3, b0, b1);
        }
    }

    // epilogue: fp32 acc -> fp16 global store
    int rA = rowBase + rw + (lane >> 2);
    int rB = rA + 8;
    int colb = (lane & 3) * 2;
#pragma unroll
    for (int nc = 0; nc < NC; nc++) {
        int col = nc * 8 + colb;
        if (rA < nrows)
            *(__half2*)&Yh[(size_t)rA * M + col] = __floats2half2_rn(acc[nc][0], acc[nc][1]);
        if (rB < nrows)
            *(__half2*)&Yh[(size_t)rB * M + col] = __floats2half2_rn(acc[nc][2], acc[nc][3]);
    }
}

// ----------------------------------------------------- sparse aggregation, M=64
// TWO nodes per warp; lane owns 4 features via one 8B fp16 gather per edge
// (full row = ONE 128B line). fp32 accumulate; fused bias+relu(+residual).
__global__ void agg64_kernel(const __half* __restrict__ suph,
                             const float* __restrict__ bias,
                             float* hout, const float* resid, int has_resid) {
    int gw   = (blockIdx.x * blockDim.x + threadIdx.x) >> 5;
    int lane = threadIdx.x & 31;
    int hf   = lane >> 4, sub = lane & 15;
    int node = gw * 2 + hf;
    if (node >= NNODES) return;
    int e   = g_rowptr[node];
    int end = g_rowptr[node + 1];
    float4 a = make_float4(0.f, 0.f, 0.f, 0.f);
    for (; e + 4 <= end; e += 4) {
        int2 e0 = g_edge[e], e1 = g_edge[e + 1], e2 = g_edge[e + 2], e3 = g_edge[e + 3];
        uint2 r0 = *(const uint2*)&suph[(size_t)e0.x * 64 + sub * 4];
        uint2 r1 = *(const uint2*)&suph[(size_t)e1.x * 64 + sub * 4];
        uint2 r2 = *(const uint2*)&suph[(size_t)e2.x * 64 + sub * 4];
        uint2 r3 = *(const uint2*)&suph[(size_t)e3.x * 64 + sub * 4];
        float w0 = __int_as_float(e0.y), w1 = __int_as_float(e1.y);
        float w2 = __int_as_float(e2.y), w3 = __int_as_float(e3.y);
        float2 fa, fb;
        h4_to_f4(r0, fa, fb);
        a.x = fmaf(fa.x, w0, a.x); a.y = fmaf(fa.y, w0, a.y);
        a.z = fmaf(fb.x, w0, a.z); a.w = fmaf(fb.y, w0, a.w);
        h4_to_f4(r1, fa, fb);
        a.x = fmaf(fa.x, w1, a.x); a.y = fmaf(fa.y, w1, a.y);
        a.z = fmaf(fb.x, w1, a.z); a.w = fmaf(fb.y, w1, a.w);
        h4_to_f4(r2, fa, fb);
        a.x = fmaf(fa.x, w2, a.x); a.y = fmaf(fa.y, w2, a.y);
        a.z = fmaf(fb.x, w2, a.z); a.w = fmaf(fb.y, w2, a.w);
        h4_to_f4(r3, fa, fb);
        a.x = fmaf(fa.x, w3, a.x); a.y = fmaf(fa.y, w3, a.y);
        a.z = fmaf(fb.x, w3, a.z); a.w = fmaf(fb.y, w3, a.w);
    }
    for (; e < end; e++) {
        int2 ed = g_edge[e];
        uint2 rv = *(const uint2*)&suph[(size_t)ed.x * 64 + sub * 4];
        float w = __int_as_float(ed.y);
        float2 fa, fb;
        h4_to_f4(rv, fa, fb);
        a.x = fmaf(fa.x, w, a.x); a.y = fmaf(fa.y, w, a.y);
        a.z = fmaf(fb.x, w, a.z); a.w = fmaf(fb.y, w, a.w);
    }
    float4 bv = ((const float4*)bias)[sub];
    a.x = fmaxf(a.x + bv.x, 0.f);
    a.y = fmaxf(a.y + bv.y, 0.f);
    a.z = fmaxf(a.z + bv.z, 0.f);
    a.w = fmaxf(a.w + bv.w, 0.f);
    if (has_resid) {               // resid may alias hout: same-element RMW only
        float4 rv = ((const float4*)(resid + (size_t)node * 64))[sub];
        a.x += rv.x; a.y += rv.y; a.z += rv.z; a.w += rv.w;
    }
    ((float4*)(hout + (size_t)node * 64))[sub] = a;
}

// ------------------------------------------- sparse aggregation + log_softmax, M=40
__global__ void agg40_kernel(const __half* __restrict__ suph,
                             const float* __restrict__ bias,
                             float* __restrict__ out) {
    int gw   = (blockIdx.x * blockDim.x + threadIdx.x) >> 5;
    int lane = threadIdx.x & 31;
    int hf   = lane >> 4, sub = lane & 15;
    int node = gw * 2 + hf;
    if (node >= NNODES) return;
    const bool act = (sub < 10);
    int e   = g_rowptr[node];
    int end = g_rowptr[node + 1];
    float4 a = make_float4(0.f, 0.f, 0.f, 0.f);
    for (; e + 4 <= end; e += 4) {
        int2 e0 = g_edge[e], e1 = g_edge[e + 1], e2 = g_edge[e + 2], e3 = g_edge[e + 3];
        uint2 r0 = make_uint2(0, 0), r1 = r0, r2 = r0, r3 = r0;
        if (act) {
            r0 = *(const uint2*)&suph[(size_t)e0.x * 40 + sub * 4];
            r1 = *(const uint2*)&suph[(size_t)e1.x * 40 + sub * 4];
            r2 = *(const uint2*)&suph[(size_t)e2.x * 40 + sub * 4];
            r3 = *(const uint2*)&suph[(size_t)e3.x * 40 + sub * 4];
        }
        float w0 = __int_as_float(e0.y), w1 = __int_as_float(e1.y);
        float w2 = __int_as_float(e2.y), w3 = __int_as_float(e3.y);
        float2 fa, fb;
        h4_to_f4(r0, fa, fb);
        a.x = fmaf(fa.x, w0, a.x); a.y = fmaf(fa.y, w0, a.y);
        a.z = fmaf(fb.x, w0, a.z); a.w = fmaf(fb.y, w0, a.w);
        h4_to_f4(r1, fa, fb);
        a.x = fmaf(fa.x, w1, a.x); a.y = fmaf(fa.y, w1, a.y);
        a.z = fmaf(fb.x, w1, a.z); a.w = fmaf(fb.y, w1, a.w);
        h4_to_f4(r2, fa, fb);
        a.x = fmaf(fa.x, w2, a.x); a.y = fmaf(fa.y, w2, a.y);
        a.z = fmaf(fb.x, w2, a.z); a.w = fmaf(fb.y, w2, a.w);
        h4_to_f4(r3, fa, fb);
        a.x = fmaf(fa.x, w3, a.x); a.y = fmaf(fa.y, w3, a.y);
        a.z = fmaf(fb.x, w3, a.z); a.w = fmaf(fb.y, w3, a.w);
    }
    for (; e < end; e++) {
        int2 ed = g_edge[e];
        uint2 rv = make_uint2(0, 0);
        if (act) rv = *(const uint2*)&suph[(size_t)ed.x * 40 + sub * 4];
        float w = __int_as_float(ed.y);
        float2 fa, fb;
        h4_to_f4(rv, fa, fb);
        a.x = fmaf(fa.x, w, a.x); a.y = fmaf(fa.y, w, a.y);
        a.z = fmaf(fb.x, w, a.z); a.w = fmaf(fb.y, w, a.w);
    }
    if (act) {
        float4 bv = ((const float4*)bias)[sub];
        a.x += bv.x; a.y += bv.y; a.z += bv.z; a.w += bv.w;
    }

    // log_softmax over 40 features held by lanes sub<10 (4 each); width-16 reduce
    float m = act ? fmaxf(fmaxf(a.x, a.y), fmaxf(a.z, a.w)) : -3.4e38f;
#pragma unroll
    for (int o = 8; o; o >>= 1) m = fmaxf(m, __shfl_xor_sync(0xffffffffu, m, o, 16));
    float ssum = act ? (__expf(a.x - m) + __expf(a.y - m) +
                        __expf(a.z - m) + __expf(a.w - m)) : 0.f;
#pragma unroll
    for (int o = 8; o; o >>= 1) ssum += __shfl_xor_sync(0xffffffffu, ssum, o, 16);
    float L = m + __logf(ssum);

    if (act) {
        float4 o4; o4.x = a.x - L; o4.y = a.y - L; o4.z = a.z - L; o4.w = a.w - L;
        ((float4*)(out + (size_t)node * 40))[sub] = o4;
    }
}

// ---------------------------------------------------------------- launch
extern "C" void kernel_launch(void* const* d_in, const int* in_sizes, int n_in,
                              void* d_out, int out_size) {
    const float* x   = (const float*)d_in[0];
    const int*   src = (const int*)d_in[1];
    const int*   tgt = (const int*)d_in[2];
    const float* mw  = (const float*)d_in[3];
    const float* W0  = (const float*)d_in[4];  const float* b0 = (const float*)d_in[5];
    const float* W1  = (const float*)d_in[6];  const float* b1 = (const float*)d_in[7];
    const float* W2  = (const float*)d_in[8];  const float* b2 = (const float*)d_in[9];
    const float* W3  = (const float*)d_in[10]; const float* b3 = (const float*)d_in[11];
    float* out = (float*)d_out;

    // smem (halfs * 2 bytes): 128*(K+8) + K*(M+8)
    const int S0 = (128 * 136 + 128 * 72) * 2;   // 53248 (opt-in)
    const int S1 = (128 * 72 + 64 * 72) * 2;     // 27648
    const int S3 = (128 * 72 + 64 * 48) * 2;     // 24576
    cudaFuncSetAttribute(gemm_kernel<128, 64>, cudaFuncAttributeMaxDynamicSharedMemorySize, S0);

    void* p;
    cudaGetSymbolAddress(&p, g_suph);  __half* sup = (__half*)p;
    cudaGetSymbolAddress(&p, g_h);     float*  h   = (float*)p;
    void* pcnt; cudaGetSymbolAddress(&pcnt, g_counts);

    // ---- CSR build (serial; parallel 3-phase scan) ----
    cudaMemsetAsync(pcnt, 0, NNODES * sizeof(int), 0);
    hist_kernel<<<(NEDGES + 255) / 256, 256>>>(tgt);
    scanA_kernel<<<SCANB, 256>>>();
    scanB_kernel<<<1, 512>>>();
    scanC_kernel<<<SCANB, 256>>>();
    scatter_kernel<<<(NEDGES + 255) / 256, 256>>>(src, tgt, mw);

    const int gblocks  = (NNODES + 127) / 128;
    const int a2blocks = (((NNODES + 1) / 2) * 32 + 255) / 256;   // 2 nodes/warp

    // layer 0: h = relu(A @ (x W0) + b0)
    gemm_kernel<128, 64><<<gblocks, 256, S0>>>(x, W0, sup, NNODES);
    agg64_kernel<<<a2blocks, 256>>>(sup, b0, h, nullptr, 0);
    // layer 1: h = relu(A @ (h W1) + b1) + h
    gemm_kernel<64, 64><<<gblocks, 256, S1>>>(h, W1, sup, NNODES);
    agg64_kernel<<<a2blocks, 256>>>(sup, b1, h, h, 1);
    // layer 2
    gemm_kernel<64, 64><<<gblocks, 256, S1>>>(h, W2, sup, NNODES);
    agg64_kernel<<<a2blocks, 256>>>(sup, b2, h, h, 1);
    // layer 3: out = log_softmax(A @ (h W3) + b3)
    gemm_kernel<64, 40><<<gblocks, 256, S3>>>(h, W3, sup, NNODES);
    agg40_kernel<<<a2blocks, 256>>>(sup, b3, out);
}